// round 9
// baseline (speedup 1.0000x reference)
#include <cuda_runtime.h>
#include <cstdint>

#define SEQ   2048
#define HID   512
#define TAPS  64
#define SC    64        // seq rows per CTA
#define UGRP  8         // rows per group
#define HTAPS 32        // taps per thread-half
#define NPAIR 256       // u64 channel-pairs per row
#define RING  80        // ring rows in smem

typedef unsigned long long u64;

__device__ __forceinline__ u64 fma2(u64 a, u64 b, u64 c) {
    u64 d;
    asm("fma.rn.f32x2 %0, %1, %2, %3;" : "=l"(d) : "l"(a), "l"(b), "l"(c));
    return d;
}
__device__ __forceinline__ u64 add2(u64 a, u64 b) {
    u64 d;
    asm("add.rn.f32x2 %0, %1, %2;" : "=l"(d) : "l"(a), "l"(b));
    return d;
}
__device__ __forceinline__ float lo32(u64 v) { return __uint_as_float((unsigned)v); }
__device__ __forceinline__ float hi32(u64 v) { return __uint_as_float((unsigned)(v >> 32)); }
__device__ __forceinline__ u64 pack2(float l, float h) {
    return ((u64)__float_as_uint(h) << 32) | (u64)__float_as_uint(l);
}

#define CP8(dst_u32, src_ptr) \
    asm volatile("cp.async.ca.shared.global [%0], [%1], 8;" :: "r"(dst_u32), "l"(src_ptr))
#define CPCOMMIT() asm volatile("cp.async.commit_group;" ::: "memory")
#define CPWAIT0()  asm volatile("cp.async.wait_group 0;"  ::: "memory")
#define BARH0()    asm volatile("bar.sync 1, 256;" ::: "memory")

// Fused circular depthwise conv (64 taps, f32x2) + residual + LayerNorm.
// 512 threads = 256 channel-pairs x 2 tap-halves. Input streams through a
// cp.async-fed smem ring; each half computes 32 taps via a static 8-register
// band. h=1 warps store partials + prefetch; h=0 warps combine, LayerNorm
// (named barrier among the 8 h=0 warps only) and store the output.
extern __shared__ u64 dsm[];

__global__ __launch_bounds__(512, 1) void fconv_ln_kernel(
    const float* __restrict__ x,
    const float* __restrict__ w,
    const float* __restrict__ gamma,
    const float* __restrict__ beta,
    float* __restrict__ out)
{
    u64*    ring = dsm;                                     // [RING][NPAIR]
    u64*    part = dsm + RING * NPAIR;                      // [UGRP][NPAIR]
    float2* red  = reinterpret_cast<float2*>(part + UGRP * NPAIR); // [8][8]
    float2* fin  = red + 64;                                        // [8]

    const int tid  = threadIdx.x;
    const int lane = tid & 31;
    const int widx = tid >> 5;
    const int p    = tid & (NPAIR - 1);
    const int h    = tid >> 8;            // tap half: taps [32h, 32h+32)
    const int b    = blockIdx.y;
    const int s0   = blockIdx.x * SC;

    const u64* __restrict__ xb =
        reinterpret_cast<const u64*>(x) + (size_t)b * SEQ * NPAIR;
    u64* __restrict__ op =
        reinterpret_cast<u64*>(out) + ((size_t)b * SEQ + s0) * NPAIR + p;

    const unsigned rbase = (unsigned)__cvta_generic_to_shared(ring);
    const u64* __restrict__ ringp = ring + p;

    // Prologue fill: rows s0-63 .. s0+7 -> slots 1..71; halves interleave rows.
#pragma unroll 1
    for (int i = h; i < 71; i += 2) {
        int rowg = (s0 - 63 + i + SEQ) & (SEQ - 1);
        CP8(rbase + (unsigned)(((i + 1) * NPAIR + p) * 8),
            xb + (size_t)rowg * NPAIR + p);
    }
    CPCOMMIT();

    // This half's 32 tap-weights for this channel pair.
    u64 wr[HTAPS];
#pragma unroll
    for (int t = 0; t < HTAPS; ++t)
        wr[t] = reinterpret_cast<const u64*>(w)[(HTAPS * h + t) * NPAIR + p];
    const u64 g2 = reinterpret_cast<const u64*>(gamma)[p];
    const u64 b2 = reinterpret_cast<const u64*>(beta)[p];

    const float ksc = 0.022097086912079608f;   // 1/sqrt(2048)
    const u64 sc2 = pack2(ksc, ksc);

#pragma unroll 1
    for (int g = 0; g < SC / UGRP; ++g) {
        CPWAIT0();
        __syncthreads();   // sync0: prefetched rows visible; prior part reads done

        // Slot of row sb = s0+8g is sli; this half's band starts at row sb-32h.
        int sli = 8 * g + 64; if (sli >= RING) sli -= RING;
        int bsl = sli - HTAPS * h; if (bsl < 0) bsl += RING;

        u64 band[8];
#pragma unroll
        for (int i = 0; i < 8; ++i) band[i] = ringp[(bsl + i) * NPAIR];

        u64 acc[8];
#pragma unroll
        for (int j = 0; j < 8; ++j) acc[j] = 0ull;

        // Descending history stream: rows sb-32h-1-t for t = 0..30.
        int sl = (bsl == 0) ? (RING - 1) : (bsl - 1);
#pragma unroll
        for (int t = 0; t < HTAPS; ++t) {
            u64 nv = 0ull;
            if (t < HTAPS - 1) {
                nv = ringp[sl * NPAIR];
                sl = (sl == 0) ? (RING - 1) : (sl - 1);
            }
#pragma unroll
            for (int j = 0; j < 8; ++j)
                acc[j] = fma2(wr[t], band[(j - t) & 7], acc[j]);
            if (t < HTAPS - 1) band[(7 - t) & 7] = nv;
        }

        if (h) {
#pragma unroll
            for (int j = 0; j < 8; ++j) part[j * NPAIR + p] = acc[j];
        }
        __syncthreads();   // sync_c: partials visible; all ring reads of group done

        if (h) {
            // Prefetch next group's rows into slots 8g+72..79 (mod RING).
            if (g < SC / UGRP - 1) {
                int slp = 8 * g + 72; if (slp >= RING) slp -= RING;
#pragma unroll
                for (int i = 0; i < 8; ++i) {
                    int rowg = (s0 + 8 * g + 8 + i) & (SEQ - 1);
                    CP8(rbase + (unsigned)(((slp + i) * NPAIR + p) * 8),
                        xb + (size_t)rowg * NPAIR + p);
                }
            }
            CPCOMMIT();
        } else {
            // Combine halves, scale, add residual (rows sb..sb+7 at sli..sli+7).
#pragma unroll
            for (int j = 0; j < 8; ++j) {
                u64 tot = add2(acc[j], part[j * NPAIR + p]);
                acc[j] = fma2(tot, sc2, ringp[(sli + j) * NPAIR]);
            }

            // LayerNorm stage 1: per-warp partial sums per row.
#pragma unroll
            for (int j = 0; j < 8; ++j) {
                float a = lo32(acc[j]), c = hi32(acc[j]);
                float s = a + c, q = a * a + c * c;
#pragma unroll
                for (int o = 16; o > 0; o >>= 1) {
                    s += __shfl_xor_sync(0xFFFFFFFFu, s, o);
                    q += __shfl_xor_sync(0xFFFFFFFFu, q, o);
                }
                if (lane == 0) red[j * 8 + widx] = make_float2(s, q);
            }
            BARH0();   // red ready (h=0 warps only)

            // Stage 2: warp widx finalizes row widx.
            {
                float2 pr = red[widx * 8 + (lane & 7)];
                float s = pr.x, q = pr.y;
#pragma unroll
                for (int o = 4; o > 0; o >>= 1) {
                    s += __shfl_xor_sync(0xFFFFFFFFu, s, o);
                    q += __shfl_xor_sync(0xFFFFFFFFu, q, o);
                }
                if (lane == 0) {
                    float mean = s * (1.0f / HID);
                    float var  = q * (1.0f / HID) - mean * mean;
                    fin[widx] = make_float2(mean, rsqrtf(var + 1e-12f));
                }
            }
            BARH0();   // fin ready

            // Normalize + coalesced store.
#pragma unroll
            for (int j = 0; j < 8; ++j) {
                float2 mi = fin[j];
                float a = (lo32(acc[j]) - mi.x) * mi.y;
                float c = (hi32(acc[j]) - mi.x) * mi.y;
                op[(8 * g + j) * NPAIR] =
                    pack2(lo32(g2) * a + lo32(b2), hi32(g2) * c + hi32(b2));
            }
        }
    }
}

extern "C" void kernel_launch(void* const* d_in, const int* in_sizes, int n_in,
                              void* d_out, int out_size)
{
    const float* x     = (const float*)d_in[0];   // [B, 2048, 512] f32
    const float* w     = (const float*)d_in[1];   // [1, 64, 512]   f32
    const float* gamma = (const float*)d_in[2];   // [512]          f32
    const float* beta  = (const float*)d_in[3];   // [512]          f32
    float* out = (float*)d_out;

    const int B = in_sizes[0] / (SEQ * HID);
    const int smem = (RING * NPAIR + UGRP * NPAIR) * 8 + 64 * 8 + 8 * 8; // ~181KB

    static bool attr_set = false;
    if (!attr_set) {
        cudaFuncSetAttribute(fconv_ln_kernel,
                             cudaFuncAttributeMaxDynamicSharedMemorySize, smem);
        attr_set = true;
    }

    dim3 grid(SEQ / SC, B);   // (32, B)
    fconv_ln_kernel<<<grid, 512, smem>>>(x, w, gamma, beta, out);
}

// round 10
// speedup vs baseline: 1.0613x; 1.0613x over previous
#include <cuda_runtime.h>
#include <cstdint>

#define SEQ   2048
#define HID   512
#define TAPS  64
#define SC    64        // seq rows per CTA
#define UGRP  8         // rows per group
#define NG    (SC / UGRP)
#define NPAIR 256       // u64 channel-pairs per row (= threads)
#define RING  88        // ring rows in smem (64 hist + 8 cur + 2x8 prefetch)

typedef unsigned long long u64;

__device__ __forceinline__ u64 fma2(u64 a, u64 b, u64 c) {
    u64 d;
    asm("fma.rn.f32x2 %0, %1, %2, %3;" : "=l"(d) : "l"(a), "l"(b), "l"(c));
    return d;
}
__device__ __forceinline__ float lo32(u64 v) { return __uint_as_float((unsigned)v); }
__device__ __forceinline__ float hi32(u64 v) { return __uint_as_float((unsigned)(v >> 32)); }
__device__ __forceinline__ u64 pack2(float l, float h) {
    return ((u64)__float_as_uint(h) << 32) | (u64)__float_as_uint(l);
}

#define CP8(dst_u32, src_ptr) \
    asm volatile("cp.async.ca.shared.global [%0], [%1], 8;" :: "r"(dst_u32), "l"(src_ptr))
#define CPCOMMIT() asm volatile("cp.async.commit_group;" ::: "memory")
#define CPWAIT1()  asm volatile("cp.async.wait_group 1;"  ::: "memory")

// Fused circular depthwise conv (64 taps, f32x2) + residual + LayerNorm.
// 256 threads = 256 channel-pairs (all 512 channels); each thread computes all
// 64 taps from a cp.async ring (depth-2 prefetch, wait_group 1) via a static
// 8-register band with 2-deep LDS lookahead. 2 barriers/group; LN stage 2 is
// warp-redundant (no third barrier).
extern __shared__ u64 ring[];   // [RING][NPAIR] + red[8][9] float2

__global__ __launch_bounds__(256) void fconv_ln_kernel(
    const float* __restrict__ x,
    const float* __restrict__ w,
    const float* __restrict__ gamma,
    const float* __restrict__ beta,
    float* __restrict__ out)
{
    const int tid  = threadIdx.x;
    const int lane = tid & 31;
    const int widx = tid >> 5;
    const int b    = blockIdx.y;
    const int s0   = blockIdx.x * SC;

    float2* red = reinterpret_cast<float2*>(ring + RING * NPAIR);  // [8][9] padded

    const u64* __restrict__ xb =
        reinterpret_cast<const u64*>(x) + (size_t)b * SEQ * NPAIR;
    u64* __restrict__ op =
        reinterpret_cast<u64*>(out) + ((size_t)b * SEQ + s0) * NPAIR + tid;

    const unsigned rbase = (unsigned)__cvta_generic_to_shared(ring);
    const u64* __restrict__ ringp = ring + tid;

    // Prologue: rows s0-63..s0+7 -> slots 1..71 (commit 1); rows s0+8..15 ->
    // slots 72..79 (commit 2).  slot(row) = (row - s0 + 64) mod RING.
#pragma unroll 1
    for (int i = 0; i < 71; ++i) {
        int rowg = (s0 - 63 + i + SEQ) & (SEQ - 1);
        CP8(rbase + (unsigned)(((i + 1) * NPAIR + tid) * 8),
            xb + (size_t)rowg * NPAIR + tid);
    }
    CPCOMMIT();
#pragma unroll
    for (int i = 0; i < UGRP; ++i) {
        int rowg = (s0 + 8 + i) & (SEQ - 1);
        CP8(rbase + (unsigned)(((72 + i) * NPAIR + tid) * 8),
            xb + (size_t)rowg * NPAIR + tid);
    }
    CPCOMMIT();

    // Weights (64 taps), gamma, beta — LDGs overlap the prologue fill.
    u64 wr[TAPS];
#pragma unroll
    for (int t = 0; t < TAPS; ++t)
        wr[t] = reinterpret_cast<const u64*>(w)[t * NPAIR + tid];
    const u64 g2 = reinterpret_cast<const u64*>(gamma)[tid];
    const u64 b2 = reinterpret_cast<const u64*>(beta)[tid];

    const float ksc = 0.022097086912079608f;   // 1/sqrt(2048)
    const u64 sc2 = pack2(ksc, ksc);

#pragma unroll 1
    for (int g = 0; g < NG; ++g) {
        CPWAIT1();          // all but the most recent commit complete
        __syncthreads();    // sync0: this group's rows visible; red reusable

        // Prefetch for group g+2 into slots (8g+80..87) mod RING — disjoint
        // from group g reads (8g+1..71) and g+1 reads (8g+9..79).
        if (g < NG - 2) {
            int slp = 8 * g + 80; if (slp >= RING) slp -= RING;
#pragma unroll
            for (int i = 0; i < UGRP; ++i) {
                int rowg = (s0 + 8 * g + 16 + i) & (SEQ - 1);
                CP8(rbase + (unsigned)((((slp + i) % RING) * NPAIR + tid) * 8),
                    xb + (size_t)rowg * NPAIR + tid);
            }
        }
        CPCOMMIT();   // always commit (possibly empty) to keep wait_group sane

        // Band init: rows sb..sb+7 at contiguous slots sli..sli+7 (no wrap:
        // 8g+64 mod 88 is a multiple of 8; 88/8 = 11).
        int sli = 8 * g + 64; if (sli >= RING) sli -= RING;
        u64 band[8];
#pragma unroll
        for (int i = 0; i < 8; ++i) band[i] = ringp[(sli + i) * NPAIR];

        u64 acc[8];
#pragma unroll
        for (int j = 0; j < 8; ++j) acc[j] = 0ull;

        // Descending history stream with 2-deep LDS lookahead.
        int sl = 8 * g + 63; if (sl >= RING) sl -= RING;   // slot of row sb-1
        u64 nvq[2];
        nvq[0] = ringp[sl * NPAIR]; sl = sl ? sl - 1 : RING - 1;  // row sb-1
        nvq[1] = ringp[sl * NPAIR]; sl = sl ? sl - 1 : RING - 1;  // row sb-2
#pragma unroll
        for (int t = 0; t < TAPS; ++t) {
            u64 append = nvq[t & 1];                  // row sb-1-t
            if (t < TAPS - 3) {                       // load row sb-3-t
                nvq[t & 1] = ringp[sl * NPAIR];
                sl = sl ? sl - 1 : RING - 1;
            }
#pragma unroll
            for (int j = 0; j < 8; ++j)
                acc[j] = fma2(wr[t], band[(j - t) & 7], acc[j]);
            if (t < TAPS - 1) band[(7 - t) & 7] = append;
        }

        // Scale + residual (rows sb..sb+7 re-read from slots sli..sli+7).
#pragma unroll
        for (int j = 0; j < 8; ++j)
            acc[j] = fma2(acc[j], sc2, ringp[(sli + j) * NPAIR]);

        // LayerNorm stage 1: per-warp partial (sum, sumsq) per row.
#pragma unroll
        for (int j = 0; j < 8; ++j) {
            float a = lo32(acc[j]), c = hi32(acc[j]);
            float s = a + c, q = a * a + c * c;
#pragma unroll
            for (int o = 16; o > 0; o >>= 1) {
                s += __shfl_xor_sync(0xFFFFFFFFu, s, o);
                q += __shfl_xor_sync(0xFFFFFFFFu, q, o);
            }
            if (lane == 0) red[j * 9 + widx] = make_float2(s, q);
        }
        __syncthreads();   // sync1: red ready

        // Stage 2, warp-redundant: lanes 0..7 reduce row=lane; broadcast.
        float mean = 0.f, inv = 0.f;
        if (lane < 8) {
            float s = 0.f, q = 0.f;
#pragma unroll
            for (int i = 0; i < 8; ++i) {
                float2 pr = red[lane * 9 + i];
                s += pr.x; q += pr.y;
            }
            mean = s * (1.0f / HID);
            float var = q * (1.0f / HID) - mean * mean;
            inv = rsqrtf(var + 1e-12f);
        }

        // Normalize + coalesced store (2KB per row).
#pragma unroll
        for (int j = 0; j < 8; ++j) {
            float mj = __shfl_sync(0xFFFFFFFFu, mean, j);
            float ij = __shfl_sync(0xFFFFFFFFu, inv,  j);
            float a = (lo32(acc[j]) - mj) * ij;
            float c = (hi32(acc[j]) - mj) * ij;
            op[(8 * g + j) * NPAIR] =
                pack2(lo32(g2) * a + lo32(b2), hi32(g2) * c + hi32(b2));
        }
    }
}

extern "C" void kernel_launch(void* const* d_in, const int* in_sizes, int n_in,
                              void* d_out, int out_size)
{
    const float* x     = (const float*)d_in[0];   // [B, 2048, 512] f32
    const float* w     = (const float*)d_in[1];   // [1, 64, 512]   f32
    const float* gamma = (const float*)d_in[2];   // [512]          f32
    const float* beta  = (const float*)d_in[3];   // [512]          f32
    float* out = (float*)d_out;

    const int B = in_sizes[0] / (SEQ * HID);
    const int smem = RING * NPAIR * 8 + 8 * 9 * 8;   // ring + red ≈ 176.6KB

    static bool attr_set = false;
    if (!attr_set) {
        cudaFuncSetAttribute(fconv_ln_kernel,
                             cudaFuncAttributeMaxDynamicSharedMemorySize, smem);
        attr_set = true;
    }

    dim3 grid(SEQ / SC, B);   // (32, B)
    fconv_ln_kernel<<<grid, 256, smem>>>(x, w, gamma, beta, out);
}